// round 15
// baseline (speedup 1.0000x reference)
#include <cuda_runtime.h>
#include <cuda_bf16.h>
#include <cstdint>
#include <math.h>

// ---------------- problem constants ----------------
#define B_SZ   1024
#define GF     512
#define KDIM   512
#define OUTF   512
#define NLEAF  64
#define NGATE  63
#define NTOT   (OUTF * NLEAF)   // 32768

// ---------------- GEMM config (int8) ----------------
#define BM 128
#define BN 256
#define BKB 64                  // int8 bytes per chunk (k extent 64)
#define NCH 24                  // 3 passes * 8 chunks
#define ROWB 80                 // smem row stride bytes (64 data + 16 pad)
#define A_STAGE_B (BM * ROWB)               // 10240
#define B_STAGE_B (BN * ROWB)               // 20480
#define STAGE_B   (A_STAGE_B + B_STAGE_B)   // 30720
#define NSTAGE 6
#define SM_TOTAL (STAGE_B * NSTAGE)         // 184320
#define NTHREADS 512
#define WQ_SMEM (512 * 65 * 4)              // 133120

// ---------------- scratch ----------------
__device__ float        g_P[B_SZ * NLEAF];
__device__ float        g_sx[B_SZ];
__device__ float        g_sw[NTOT];
__device__ signed char  g_X0[B_SZ * KDIM];
__device__ signed char  g_X1[B_SZ * KDIM];
__device__ signed char  g_W0[(size_t)NTOT * KDIM];
__device__ signed char  g_W1[(size_t)NTOT * KDIM];

// ---------------- helpers ----------------
__device__ __forceinline__ uint32_t smem_u32(const void* p) {
    uint32_t a;
    asm("{ .reg .u64 t; cvta.to.shared.u64 t, %1; cvt.u32.u64 %0, t; }" : "=r"(a) : "l"(p));
    return a;
}
__device__ __forceinline__ void cp_async16(uint32_t dst, const void* src) {
    asm volatile("cp.async.cg.shared.global [%0], [%1], 16;" :: "r"(dst), "l"(src) : "memory");
}
__device__ __forceinline__ void cp_commit() {
    asm volatile("cp.async.commit_group;" ::: "memory");
}
__device__ __forceinline__ void cp_wait2() {
    asm volatile("cp.async.wait_group 2;" ::: "memory");
}
__device__ __forceinline__ void ldsm_x4(uint32_t* r, uint32_t addr) {
    asm volatile("ldmatrix.sync.aligned.m8n8.x4.shared.b16 {%0,%1,%2,%3}, [%4];"
                 : "=r"(r[0]), "=r"(r[1]), "=r"(r[2]), "=r"(r[3]) : "r"(addr));
}
__device__ __forceinline__ void mma_s8(int* d, const uint32_t* a, uint32_t b0, uint32_t b1) {
    asm volatile(
        "mma.sync.aligned.m16n8k32.row.col.s32.s8.s8.s32 "
        "{%0,%1,%2,%3}, {%4,%5,%6,%7}, {%8,%9}, {%0,%1,%2,%3};"
        : "+r"(d[0]), "+r"(d[1]), "+r"(d[2]), "+r"(d[3])
        : "r"(a[0]), "r"(a[1]), "r"(a[2]), "r"(a[3]), "r"(b0), "r"(b1));
}

// ---------------- kernel 1: gating + leaf probs ----------------
__global__ void __launch_bounds__(256) gating_kernel(
    const float* __restrict__ xg, const float* __restrict__ gw, const float* __restrict__ gb)
{
    __shared__ float xs[4][GF];
    __shared__ float gs[4][64];
    int b0 = blockIdx.x * 4;
    int tid = threadIdx.x;
    for (int v = tid; v < 4 * GF; v += 256) {
        int r = v >> 9, k = v & (GF - 1);
        xs[r][k] = xg[(b0 + r) * GF + k];
    }
    __syncthreads();
    int r = tid >> 6;
    int g = tid & 63;
    if (g < NGATE) {
        float a0 = 0.f, a1 = 0.f;
        #pragma unroll 4
        for (int k = 0; k < GF; k += 2) {
            a0 += xs[r][k]     * gw[k * NGATE + g];
            a1 += xs[r][k + 1] * gw[(k + 1) * NGATE + g];
        }
        float acc = a0 + a1 + gb[g];
        gs[r][g] = 1.0f / (1.0f + expf(-acc));
    }
    __syncthreads();
    int l = g;
    float prob = 1.0f;
    #pragma unroll
    for (int d = 0; d < 6; d++) {
        int j = l >> (6 - d);
        int idx = (1 << d) - 1 + j;
        int bit = (l >> (5 - d)) & 1;
        float gv = gs[r][idx];
        prob *= bit ? (1.0f - gv) : gv;
    }
    g_P[(b0 + r) * NLEAF + l] = prob;
}

// ---------------- kernel 2: quantize x_leaf (per-row scale, 2-level int8) ----------------
__global__ void __launch_bounds__(256) xquant_kernel(const float* __restrict__ x)
{
    int wid = threadIdx.x >> 5, lane = threadIdx.x & 31;
    int b = blockIdx.x * 8 + wid;
    const float* row = x + b * KDIM;
    float v[16];
    float amax = 0.f;
    #pragma unroll
    for (int j = 0; j < 16; j++) {
        v[j] = row[j * 32 + lane];
        amax = fmaxf(amax, fabsf(v[j]));
    }
    #pragma unroll
    for (int o = 16; o; o >>= 1) amax = fmaxf(amax, __shfl_xor_sync(0xFFFFFFFFu, amax, o));
    amax = fmaxf(amax, 1e-20f);
    float sx = amax / 127.f, inv = 127.f / amax, inv2 = 128.f / sx;
    if (lane == 0) g_sx[b] = sx;
    #pragma unroll
    for (int j = 0; j < 16; j++) {
        int q0 = __float2int_rn(v[j] * inv);
        float r = v[j] - sx * (float)q0;
        int q1 = __float2int_rn(r * inv2);
        g_X0[b * KDIM + j * 32 + lane] = (signed char)q0;
        g_X1[b * KDIM + j * 32 + lane] = (signed char)q1;
    }
}

// ---------------- kernel 3: quantize+repack pw -> W0/W1 [n=o*64+l][k=i] ----------------
__global__ void __launch_bounds__(256) wquant_kernel(const float* __restrict__ pw)
{
    extern __shared__ float t[];          // [512][65]
    __shared__ float pm[4][64];
    int o = blockIdx.x;
    const float* src = pw + (size_t)o * KDIM * NLEAF;
    int tid = threadIdx.x;
    for (int v = tid; v < KDIM * NLEAF; v += 256) {
        int i = v >> 6, l = v & 63;
        t[i * 65 + l] = src[v];
    }
    __syncthreads();
    {
        int l = tid & 63, part = tid >> 6;
        float m = 0.f;
        for (int i = part * 128; i < part * 128 + 128; i++)
            m = fmaxf(m, fabsf(t[i * 65 + l]));
        pm[part][l] = m;
    }
    __syncthreads();
    int wid = tid >> 5, lane = tid & 31;
    for (int l = wid; l < 64; l += 8) {
        float amax = fmaxf(fmaxf(pm[0][l], pm[1][l]), fmaxf(pm[2][l], pm[3][l]));
        amax = fmaxf(amax, 1e-20f);
        float sw = amax / 127.f, inv = 127.f / amax, inv2 = 128.f / sw;
        if (lane == 0) g_sw[o * 64 + l] = sw;
        size_t nrow = ((size_t)o * 64 + l) * KDIM;
        __align__(16) signed char q0v[16];
        __align__(16) signed char q1v[16];
        #pragma unroll
        for (int j = 0; j < 16; j++) {
            float w = t[(lane * 16 + j) * 65 + l];
            int q0 = __float2int_rn(w * inv);
            float r = w - sw * (float)q0;
            int q1 = __float2int_rn(r * inv2);
            q0v[j] = (signed char)q0;
            q1v[j] = (signed char)q1;
        }
        *(int4*)(g_W0 + nrow + lane * 16) = *(const int4*)q0v;
        *(int4*)(g_W1 + nrow + lane * 16) = *(const int4*)q1v;
    }
}

// ---------------- kernel 4: int8 IMMA GEMM + fused leaf contraction ----------------
// passes: c 0-7: X0*W0 (P); c 8-15: X0*W1 (Q); c 16-23: X1*W0 (Q)
__device__ __forceinline__ void issue_chunk(int c, uint32_t sbu, int tid, size_t m0, size_t n0)
{
    if (c >= NCH) { cp_commit(); return; }
    int s = c % NSTAGE;
    int pass = c >> 3;
    int koff = (c & 7) * BKB;
    const signed char* A = (pass == 2) ? g_X1 : g_X0;
    const signed char* W = (pass == 1) ? g_W1 : g_W0;
    uint32_t aBase = sbu + s * STAGE_B;
    uint32_t bBase = aBase + A_STAGE_B;
    {   // A tile: 128 rows x 64B -> 512 segs, 1/thread
        int row = tid >> 2, seg = tid & 3;
        cp_async16(aBase + row * ROWB + seg * 16, A + (m0 + row) * KDIM + koff + seg * 16);
    }
    #pragma unroll
    for (int i = 0; i < 2; i++) {   // B tile: 256 rows x 64B -> 1024 segs, 2/thread
        int idx = tid + i * NTHREADS;
        int row = idx >> 2, seg = idx & 3;
        cp_async16(bBase + row * ROWB + seg * 16, W + (n0 + row) * KDIM + koff + seg * 16);
    }
    cp_commit();
}

__global__ void __launch_bounds__(NTHREADS, 1) gemm_kernel(
    const float* __restrict__ pb, float* __restrict__ out)
{
    extern __shared__ char smem[];
    uint32_t sbu = smem_u32(smem);
    int tid = threadIdx.x;
    int wid = tid >> 5;
    int lane = tid & 31;
    int wm = wid & 3;          // 4 m-warps (32 rows)
    int wn = wid >> 2;         // 4 n-warps (64 cols = one o each)
    size_t m0 = (size_t)blockIdx.x * BM;
    size_t n0 = (size_t)blockIdx.y * BN;

    int acc[2][8][4];
    #pragma unroll
    for (int a = 0; a < 2; a++)
        #pragma unroll
        for (int b = 0; b < 8; b++)
            #pragma unroll
            for (int cc = 0; cc < 4; cc++) acc[a][b][cc] = 0;

    // ldmatrix per-lane addressing (byte units)
    int a_row = lane & 15;
    int a_kb  = (lane >> 4) * 16;
    int b_row = (lane & 7) + ((lane >> 4) << 3);
    int b_kb  = (lane & 8) * 2;

    int o = (int)(n0 >> 6) + wn;
    const float* pbrow = pb + (size_t)o * NLEAF;
    const float* swrow = g_sw + (size_t)o * NLEAF;
    float tP0[2] = {0.f, 0.f}, tP1[2] = {0.f, 0.f};
    float tB0[2] = {0.f, 0.f}, tB1[2] = {0.f, 0.f};
    float tQ0[2] = {0.f, 0.f}, tQ1[2] = {0.f, 0.f};

    issue_chunk(0, sbu, tid, m0, n0);
    issue_chunk(1, sbu, tid, m0, n0);
    issue_chunk(2, sbu, tid, m0, n0);
    issue_chunk(3, sbu, tid, m0, n0);

    for (int p = 0; p < NCH / 2; p++) {
        cp_wait2();
        __syncthreads();
        issue_chunk(2 * p + 4, sbu, tid, m0, n0);
        issue_chunk(2 * p + 5, sbu, tid, m0, n0);

        #pragma unroll
        for (int cc = 0; cc < 2; cc++) {
            int c = 2 * p + cc;
            int s = c % NSTAGE;
            uint32_t aBase = sbu + s * STAGE_B;
            uint32_t bBase = aBase + A_STAGE_B;
            #pragma unroll
            for (int kk = 0; kk < 2; kk++) {
                uint32_t af[2][4], bf[4][4];
                #pragma unroll
                for (int mi = 0; mi < 2; mi++) {
                    uint32_t addr = aBase + (uint32_t)((wm * 32 + mi * 16 + a_row) * ROWB
                                   + kk * 32 + a_kb);
                    ldsm_x4(af[mi], addr);
                }
                #pragma unroll
                for (int ni = 0; ni < 4; ni++) {
                    uint32_t addr = bBase + (uint32_t)((wn * 64 + ni * 16 + b_row) * ROWB
                                   + kk * 32 + b_kb);
                    ldsm_x4(bf[ni], addr);
                }
                #pragma unroll
                for (int mi = 0; mi < 2; mi++) {
                    #pragma unroll
                    for (int ni = 0; ni < 4; ni++) {
                        mma_s8(acc[mi][ni * 2 + 0], af[mi], bf[ni][0], bf[ni][1]);
                        mma_s8(acc[mi][ni * 2 + 1], af[mi], bf[ni][2], bf[ni][3]);
                    }
                }
            }
        }

        if (p == 3) {
            // ---- contract P pass: tP += sw*P*pleaf ; tB += pb*pleaf ; zero acc ----
            #pragma unroll
            for (int mi = 0; mi < 2; mi++) {
                size_t r0 = m0 + wm * 32 + mi * 16 + (lane >> 2);
                const float* P0 = g_P + r0 * NLEAF;
                const float* P1 = g_P + (r0 + 8) * NLEAF;
                #pragma unroll
                for (int ni = 0; ni < 4; ni++) {
                    #pragma unroll
                    for (int sub = 0; sub < 2; sub++) {
                        int nf = ni * 2 + sub;
                        int col = ni * 16 + sub * 8 + (lane & 3) * 2;
                        float2 swv = *(const float2*)(swrow + col);
                        float2 bv  = *(const float2*)(pbrow + col);
                        float2 pv0 = *(const float2*)(P0 + col);
                        float2 pv1 = *(const float2*)(P1 + col);
                        tP0[mi] += (float)acc[mi][nf][0] * swv.x * pv0.x
                                 + (float)acc[mi][nf][1] * swv.y * pv0.y;
                        tB0[mi] += bv.x * pv0.x + bv.y * pv0.y;
                        tP1[mi] += (float)acc[mi][nf][2] * swv.x * pv1.x
                                 + (float)acc[mi][nf][3] * swv.y * pv1.y;
                        tB1[mi] += bv.x * pv1.x + bv.y * pv1.y;
                        acc[mi][nf][0] = 0; acc[mi][nf][1] = 0;
                        acc[mi][nf][2] = 0; acc[mi][nf][3] = 0;
                    }
                }
            }
        }
    }

    // ---- contract Q passes, combine, reduce, store ----
    #pragma unroll
    for (int mi = 0; mi < 2; mi++) {
        size_t r0 = m0 + wm * 32 + mi * 16 + (lane >> 2);
        const float* P0 = g_P + r0 * NLEAF;
        const float* P1 = g_P + (r0 + 8) * NLEAF;
        #pragma unroll
        for (int ni = 0; ni < 4; ni++) {
            #pragma unroll
            for (int sub = 0; sub < 2; sub++) {
                int nf = ni * 2 + sub;
                int col = ni * 16 + sub * 8 + (lane & 3) * 2;
                float2 swv = *(const float2*)(swrow + col);
                float2 pv0 = *(const float2*)(P0 + col);
                float2 pv1 = *(const float2*)(P1 + col);
                tQ0[mi] += (float)acc[mi][nf][0] * swv.x * pv0.x
                         + (float)acc[mi][nf][1] * swv.y * pv0.y;
                tQ1[mi] += (float)acc[mi][nf][2] * swv.x * pv1.x
                         + (float)acc[mi][nf][3] * swv.y * pv1.y;
            }
        }
        float sxa = g_sx[r0];
        float sxb = g_sx[r0 + 8];
        float s0 = sxa * (tP0[mi] + tQ0[mi] * 0.0078125f) + tB0[mi];
        float s1 = sxb * (tP1[mi] + tQ1[mi] * 0.0078125f) + tB1[mi];
        s0 += __shfl_xor_sync(0xFFFFFFFFu, s0, 1);
        s0 += __shfl_xor_sync(0xFFFFFFFFu, s0, 2);
        s1 += __shfl_xor_sync(0xFFFFFFFFu, s1, 1);
        s1 += __shfl_xor_sync(0xFFFFFFFFu, s1, 2);
        if ((lane & 3) == 0) {
            out[r0 * OUTF + o] = s0;
            out[(r0 + 8) * OUTF + o] = s1;
        }
    }
}

// ---------------- launch ----------------
extern "C" void kernel_launch(void* const* d_in, const int* in_sizes, int n_in,
                              void* d_out, int out_size)
{
    const float* xg = (const float*)d_in[0];
    const float* xl = (const float*)d_in[1];
    const float* gw = (const float*)d_in[2];
    const float* gb = (const float*)d_in[3];
    const float* pw = (const float*)d_in[4];
    const float* pb = (const float*)d_in[5];
    float* out = (float*)d_out;

    cudaFuncSetAttribute(gemm_kernel, cudaFuncAttributeMaxDynamicSharedMemorySize, SM_TOTAL);
    cudaFuncSetAttribute(wquant_kernel, cudaFuncAttributeMaxDynamicSharedMemorySize, WQ_SMEM);

    gating_kernel<<<B_SZ / 4, 256>>>(xg, gw, gb);
    xquant_kernel<<<B_SZ / 8, 256>>>(xl);
    wquant_kernel<<<OUTF, 256, WQ_SMEM>>>(pw);
    gemm_kernel<<<dim3(B_SZ / BM, NTOT / BN), NTHREADS, SM_TOTAL>>>(pb, out);
}

// round 16
// speedup vs baseline: 2.1146x; 2.1146x over previous
#include <cuda_runtime.h>
#include <cuda_bf16.h>
#include <cstdint>
#include <math.h>

// ---------------- problem constants ----------------
#define B_SZ   1024
#define GF     512
#define KDIM   512
#define OUTF   512
#define NLEAF  64
#define NGATE  63
#define NTOT   (OUTF * NLEAF)   // 32768

// ---------------- GEMM config ----------------
#define BM 128
#define BN 256
#define BK 32                   // bf16 per chunk
#define NCH 48                  // 3 terms * 16 chunks
#define STRIDE 40               // smem row stride in bf16 (32 data + 8 pad) = 80B
#define A_STAGE_B (BM * STRIDE * 2)          // 10240
#define B_STAGE_B (BN * STRIDE * 2)          // 20480
#define STAGE_B   (A_STAGE_B + B_STAGE_B)    // 30720
#define NSTAGE 6
#define SM_TOTAL (STAGE_B * NSTAGE)          // 184320

// ---------------- scratch ----------------
__device__ float          g_P[B_SZ * NLEAF];
__device__ __nv_bfloat16  g_Axh[B_SZ * KDIM];
__device__ __nv_bfloat16  g_Axl[B_SZ * KDIM];
__device__ __nv_bfloat16  g_Wh[(size_t)NTOT * KDIM];
__device__ __nv_bfloat16  g_Wl[(size_t)NTOT * KDIM];

// ---------------- helpers ----------------
__device__ __forceinline__ uint32_t smem_u32(const void* p) {
    uint32_t a;
    asm("{ .reg .u64 t; cvta.to.shared.u64 t, %1; cvt.u32.u64 %0, t; }" : "=r"(a) : "l"(p));
    return a;
}
__device__ __forceinline__ void cp_async16(uint32_t dst, const void* src) {
    asm volatile("cp.async.cg.shared.global [%0], [%1], 16;" :: "r"(dst), "l"(src) : "memory");
}
__device__ __forceinline__ void cp_commit() {
    asm volatile("cp.async.commit_group;" ::: "memory");
}
__device__ __forceinline__ void cp_wait2() {
    asm volatile("cp.async.wait_group 2;" ::: "memory");
}
__device__ __forceinline__ void ldsm_x4(uint32_t* r, uint32_t addr) {
    asm volatile("ldmatrix.sync.aligned.m8n8.x4.shared.b16 {%0,%1,%2,%3}, [%4];"
                 : "=r"(r[0]), "=r"(r[1]), "=r"(r[2]), "=r"(r[3]) : "r"(addr));
}
__device__ __forceinline__ void mma_bf16(float* d, const uint32_t* a, uint32_t b0, uint32_t b1) {
    asm volatile(
        "mma.sync.aligned.m16n8k16.row.col.f32.bf16.bf16.f32 "
        "{%0,%1,%2,%3}, {%4,%5,%6,%7}, {%8,%9}, {%0,%1,%2,%3};"
        : "+f"(d[0]), "+f"(d[1]), "+f"(d[2]), "+f"(d[3])
        : "r"(a[0]), "r"(a[1]), "r"(a[2]), "r"(a[3]), "r"(b0), "r"(b1));
}

// ---------------- kernel 1: gating + leaf probs ----------------
__global__ void __launch_bounds__(256) gating_kernel(
    const float* __restrict__ xg, const float* __restrict__ gw, const float* __restrict__ gb)
{
    __shared__ float xs[4][GF];
    __shared__ float gs[4][64];
    int b0 = blockIdx.x * 4;
    int tid = threadIdx.x;
    for (int v = tid; v < 4 * GF; v += 256) {
        int r = v >> 9, k = v & (GF - 1);
        xs[r][k] = xg[(b0 + r) * GF + k];
    }
    __syncthreads();
    int r = tid >> 6;
    int g = tid & 63;
    if (g < NGATE) {
        float a0 = 0.f, a1 = 0.f;
        #pragma unroll 4
        for (int k = 0; k < GF; k += 2) {
            a0 += xs[r][k]     * gw[k * NGATE + g];
            a1 += xs[r][k + 1] * gw[(k + 1) * NGATE + g];
        }
        float acc = a0 + a1 + gb[g];
        gs[r][g] = 1.0f / (1.0f + expf(-acc));
    }
    __syncthreads();
    int l = g;
    float prob = 1.0f;
    #pragma unroll
    for (int d = 0; d < 6; d++) {
        int j = l >> (6 - d);
        int idx = (1 << d) - 1 + j;
        int bit = (l >> (5 - d)) & 1;
        float gv = gs[r][idx];
        prob *= bit ? (1.0f - gv) : gv;
    }
    g_P[(b0 + r) * NLEAF + l] = prob;
}

// ---------------- kernel 2: x_leaf -> bf16 hi/lo ----------------
__global__ void __launch_bounds__(256) xsplit_kernel(const float* __restrict__ x)
{
    int i = blockIdx.x * 256 + threadIdx.x;
    float v = x[i];
    __nv_bfloat16 h = __float2bfloat16(v);
    g_Axh[i] = h;
    g_Axl[i] = __float2bfloat16(v - __bfloat162float(h));
}

// ---------------- kernel 3: repack pw -> Wh/Wl [n=o*64+l][k=i] ----------------
__global__ void __launch_bounds__(256) repack_kernel(const float* __restrict__ pw)
{
    __shared__ float t[128][65];
    int o = blockIdx.x;
    const float* src = pw + (size_t)o * KDIM * NLEAF;
    int tid = threadIdx.x;
    int w = tid >> 5, lane = tid & 31;
    for (int i0 = 0; i0 < KDIM; i0 += 128) {
        __syncthreads();
        for (int v = tid; v < 128 * 64; v += 256) {
            int ii = v >> 6, l = v & 63;
            t[ii][l] = src[(i0 + ii) * NLEAF + l];
        }
        __syncthreads();
        for (int l = w; l < 64; l += 8) {
            size_t row = ((size_t)o * 64 + l) * KDIM + i0;
            for (int kk = lane; kk < 128; kk += 32) {
                float v = t[kk][l];
                __nv_bfloat16 h = __float2bfloat16(v);
                g_Wh[row + kk] = h;
                g_Wl[row + kk] = __float2bfloat16(v - __bfloat162float(h));
            }
        }
    }
}

// ---------------- kernel 4: bf16 HMMA GEMM + fused leaf contraction ----------------
__device__ __forceinline__ void issue_chunk(int c, uint32_t sbu, int tid, size_t m0, size_t n0)
{
    if (c >= NCH) { cp_commit(); return; }   // empty group keeps wait_group accounting safe
    int s = c % NSTAGE;
    int term = c >> 4;
    int koff = (c & 15) * BK;
    const __nv_bfloat16* A = (term == 1) ? g_Axl : g_Axh;
    const __nv_bfloat16* W = (term == 2) ? g_Wl : g_Wh;
    uint32_t aBase = sbu + s * STAGE_B;
    uint32_t bBase = aBase + A_STAGE_B;
    // A tile: 128 rows x 64B = 512 x 16B
    #pragma unroll
    for (int i = 0; i < 2; i++) {
        int idx = tid + i * 256;
        int row = idx >> 2, seg = idx & 3;
        cp_async16(aBase + row * (STRIDE * 2) + seg * 16,
                   A + (m0 + row) * KDIM + koff + seg * 8);
    }
    // B tile: 256 rows x 64B = 1024 x 16B
    #pragma unroll
    for (int i = 0; i < 4; i++) {
        int idx = tid + i * 256;
        int row = idx >> 2, seg = idx & 3;
        cp_async16(bBase + row * (STRIDE * 2) + seg * 16,
                   W + (n0 + row) * KDIM + koff + seg * 8);
    }
    cp_commit();
}

__global__ void __launch_bounds__(256, 1) gemm_kernel(
    const float* __restrict__ pb, float* __restrict__ out)
{
    extern __shared__ char smem[];
    uint32_t sbu = smem_u32(smem);
    int tid = threadIdx.x;
    int wid = tid >> 5;
    int lane = tid & 31;
    int wm = wid & 1;          // 2 m-warps (64 each)
    int wn = wid >> 1;         // 4 n-warps (64 each) -> one o per warp
    size_t m0 = (size_t)blockIdx.x * BM;   // m fastest: 8 m-blocks share W tiles in-wave
    size_t n0 = (size_t)blockIdx.y * BN;

    float acc[4][8][4];
    #pragma unroll
    for (int a = 0; a < 4; a++)
        #pragma unroll
        for (int b = 0; b < 8; b++)
            #pragma unroll
            for (int cc = 0; cc < 4; cc++) acc[a][b][cc] = 0.f;

    // ldmatrix per-lane address components
    int a_row = lane & 15;
    int a_k   = (lane >> 4) << 3;
    int b_row = (lane & 7) + ((lane >> 4) << 3);
    int b_k   = lane & 8;

    issue_chunk(0, sbu, tid, m0, n0);
    issue_chunk(1, sbu, tid, m0, n0);
    issue_chunk(2, sbu, tid, m0, n0);
    issue_chunk(3, sbu, tid, m0, n0);

    // 24 iterations, 2 chunks per barrier
    for (int p = 0; p < NCH / 2; p++) {
        cp_wait2();            // chunks 2p, 2p+1 complete (newest 2 groups may be in flight)
        __syncthreads();
        // prefetch next pair: stages (2p+4)%6, (2p+5)%6 were last read in iteration p-1
        issue_chunk(2 * p + 4, sbu, tid, m0, n0);
        issue_chunk(2 * p + 5, sbu, tid, m0, n0);

        #pragma unroll
        for (int cc = 0; cc < 2; cc++) {
            int c = 2 * p + cc;
            int s = c % NSTAGE;
            uint32_t aBase = sbu + s * STAGE_B;
            uint32_t bBase = aBase + A_STAGE_B;

            // ---- chunk-wide fragment hoist: issue ALL 16 ldsm before ANY mma ----
            uint32_t af[2][4][4], bf[2][4][4];
            #pragma unroll
            for (int kk = 0; kk < 2; kk++) {
                #pragma unroll
                for (int mi = 0; mi < 4; mi++) {
                    uint32_t addr = aBase + (uint32_t)((wm * 64 + mi * 16 + a_row) * (STRIDE * 2)
                                   + (kk * 16 + a_k) * 2);
                    ldsm_x4(af[kk][mi], addr);
                }
                #pragma unroll
                for (int ni = 0; ni < 4; ni++) {
                    uint32_t addr = bBase + (uint32_t)((wn * 64 + ni * 16 + b_row) * (STRIDE * 2)
                                   + (kk * 16 + b_k) * 2);
                    ldsm_x4(bf[kk][ni], addr);
                }
            }
            #pragma unroll
            for (int kk = 0; kk < 2; kk++) {
                #pragma unroll
                for (int mi = 0; mi < 4; mi++) {
                    #pragma unroll
                    for (int ni = 0; ni < 4; ni++) {
                        mma_bf16(acc[mi][ni * 2 + 0], af[kk][mi], bf[kk][ni][0], bf[kk][ni][1]);
                        mma_bf16(acc[mi][ni * 2 + 1], af[kk][mi], bf[kk][ni][2], bf[kk][ni][3]);
                    }
                }
            }
        }
    }

    // ---- fused epilogue: out[b,o] = sum_l P[b,l] * (R[b,o*64+l] + pb[o,l]) ----
    // Each warp column (wn) covers exactly one o with all 64 leaves.
    int o = (int)(n0 >> 6) + wn;
    const float* pbrow = pb + (size_t)o * NLEAF;
    #pragma unroll
    for (int mi = 0; mi < 4; mi++) {
        size_t r0 = m0 + wm * 64 + mi * 16 + (lane >> 2);
        const float* P0 = g_P + r0 * NLEAF;
        const float* P1 = g_P + (r0 + 8) * NLEAF;
        float s0 = 0.f, s1 = 0.f;
        #pragma unroll
        for (int ni = 0; ni < 4; ni++) {
            #pragma unroll
            for (int sub = 0; sub < 2; sub++) {
                int nf = ni * 2 + sub;
                int col = ni * 16 + sub * 8 + (lane & 3) * 2;
                float2 bv  = *(const float2*)(pbrow + col);
                float2 pv0 = *(const float2*)(P0 + col);
                float2 pv1 = *(const float2*)(P1 + col);
                s0 += (acc[mi][nf][0] + bv.x) * pv0.x + (acc[mi][nf][1] + bv.y) * pv0.y;
                s1 += (acc[mi][nf][2] + bv.x) * pv1.x + (acc[mi][nf][3] + bv.y) * pv1.y;
            }
        }
        s0 += __shfl_xor_sync(0xFFFFFFFFu, s0, 1);
        s0 += __shfl_xor_sync(0xFFFFFFFFu, s0, 2);
        s1 += __shfl_xor_sync(0xFFFFFFFFu, s1, 1);
        s1 += __shfl_xor_sync(0xFFFFFFFFu, s1, 2);
        if ((lane & 3) == 0) {
            out[r0 * OUTF + o] = s0;
            out[(r0 + 8) * OUTF + o] = s1;
        }
    }
}

// ---------------- launch ----------------
extern "C" void kernel_launch(void* const* d_in, const int* in_sizes, int n_in,
                              void* d_out, int out_size)
{
    const float* xg = (const float*)d_in[0];
    const float* xl = (const float*)d_in[1];
    const float* gw = (const float*)d_in[2];
    const float* gb = (const float*)d_in[3];
    const float* pw = (const float*)d_in[4];
    const float* pb = (const float*)d_in[5];
    float* out = (float*)d_out;

    cudaFuncSetAttribute(gemm_kernel, cudaFuncAttributeMaxDynamicSharedMemorySize, SM_TOTAL);

    gating_kernel<<<B_SZ / 4, 256>>>(xg, gw, gb);
    xsplit_kernel<<<(B_SZ * KDIM) / 256, 256>>>(xl);
    repack_kernel<<<OUTF, 256>>>(pw);
    gemm_kernel<<<dim3(B_SZ / BM, NTOT / BN), 256, SM_TOTAL>>>(pb, out);
}

// round 17
// speedup vs baseline: 4.5251x; 2.1400x over previous
#include <cuda_runtime.h>
#include <cuda_bf16.h>
#include <cuda_fp16.h>
#include <cstdint>
#include <math.h>

// ---------------- problem constants ----------------
#define B_SZ   1024
#define GF     512
#define KDIM   512
#define OUTF   512
#define NLEAF  64
#define NGATE  63
#define NTOT   (OUTF * NLEAF)   // 32768

// ---------------- GEMM config ----------------
#define BM 128
#define BN 256
#define BK 32                   // fp16 per chunk
#define NCH 16                  // single fp16 pass: 16 chunks of K=32
#define STRIDE 40               // smem row stride in fp16 (32 data + 8 pad) = 80B
#define A_STAGE_B (BM * STRIDE * 2)          // 10240
#define B_STAGE_B (BN * STRIDE * 2)          // 20480
#define STAGE_B   (A_STAGE_B + B_STAGE_B)    // 30720
#define NSTAGE 6
#define SM_TOTAL (STAGE_B * NSTAGE)          // 184320

// ---------------- scratch ----------------
__device__ float   g_P[B_SZ * NLEAF];
__device__ __half  g_Af[B_SZ * KDIM];
__device__ __half  g_Wf[(size_t)NTOT * KDIM];

// ---------------- helpers ----------------
__device__ __forceinline__ uint32_t smem_u32(const void* p) {
    uint32_t a;
    asm("{ .reg .u64 t; cvta.to.shared.u64 t, %1; cvt.u32.u64 %0, t; }" : "=r"(a) : "l"(p));
    return a;
}
__device__ __forceinline__ void cp_async16(uint32_t dst, const void* src) {
    asm volatile("cp.async.cg.shared.global [%0], [%1], 16;" :: "r"(dst), "l"(src) : "memory");
}
__device__ __forceinline__ void cp_commit() {
    asm volatile("cp.async.commit_group;" ::: "memory");
}
__device__ __forceinline__ void cp_wait2() {
    asm volatile("cp.async.wait_group 2;" ::: "memory");
}
__device__ __forceinline__ void ldsm_x4(uint32_t* r, uint32_t addr) {
    asm volatile("ldmatrix.sync.aligned.m8n8.x4.shared.b16 {%0,%1,%2,%3}, [%4];"
                 : "=r"(r[0]), "=r"(r[1]), "=r"(r[2]), "=r"(r[3]) : "r"(addr));
}
__device__ __forceinline__ void mma_f16(float* d, const uint32_t* a, uint32_t b0, uint32_t b1) {
    asm volatile(
        "mma.sync.aligned.m16n8k16.row.col.f32.f16.f16.f32 "
        "{%0,%1,%2,%3}, {%4,%5,%6,%7}, {%8,%9}, {%0,%1,%2,%3};"
        : "+f"(d[0]), "+f"(d[1]), "+f"(d[2]), "+f"(d[3])
        : "r"(a[0]), "r"(a[1]), "r"(a[2]), "r"(a[3]), "r"(b0), "r"(b1));
}

// ---------------- kernel 1: gating + leaf probs ----------------
__global__ void __launch_bounds__(256) gating_kernel(
    const float* __restrict__ xg, const float* __restrict__ gw, const float* __restrict__ gb)
{
    __shared__ float xs[4][GF];
    __shared__ float gs[4][64];
    int b0 = blockIdx.x * 4;
    int tid = threadIdx.x;
    for (int v = tid; v < 4 * GF; v += 256) {
        int r = v >> 9, k = v & (GF - 1);
        xs[r][k] = xg[(b0 + r) * GF + k];
    }
    __syncthreads();
    int r = tid >> 6;
    int g = tid & 63;
    if (g < NGATE) {
        float a0 = 0.f, a1 = 0.f;
        #pragma unroll 4
        for (int k = 0; k < GF; k += 2) {
            a0 += xs[r][k]     * gw[k * NGATE + g];
            a1 += xs[r][k + 1] * gw[(k + 1) * NGATE + g];
        }
        float acc = a0 + a1 + gb[g];
        gs[r][g] = 1.0f / (1.0f + expf(-acc));
    }
    __syncthreads();
    int l = g;
    float prob = 1.0f;
    #pragma unroll
    for (int d = 0; d < 6; d++) {
        int j = l >> (6 - d);
        int idx = (1 << d) - 1 + j;
        int bit = (l >> (5 - d)) & 1;
        float gv = gs[r][idx];
        prob *= bit ? (1.0f - gv) : gv;
    }
    g_P[(b0 + r) * NLEAF + l] = prob;
}

// ---------------- kernel 2: x_leaf -> fp16 ----------------
__global__ void __launch_bounds__(256) xconv_kernel(const float* __restrict__ x)
{
    int i = blockIdx.x * 256 + threadIdx.x;
    g_Af[i] = __float2half(x[i]);
}

// ---------------- kernel 3: repack pw -> Wf [n=o*64+l][k=i] (fp16) ----------------
__global__ void __launch_bounds__(256) repack_kernel(const float* __restrict__ pw)
{
    __shared__ float t[128][65];
    int o = blockIdx.x;
    const float* src = pw + (size_t)o * KDIM * NLEAF;
    int tid = threadIdx.x;
    int w = tid >> 5, lane = tid & 31;
    for (int i0 = 0; i0 < KDIM; i0 += 128) {
        __syncthreads();
        for (int v = tid; v < 128 * 64; v += 256) {
            int ii = v >> 6, l = v & 63;
            t[ii][l] = src[(i0 + ii) * NLEAF + l];
        }
        __syncthreads();
        for (int l = w; l < 64; l += 8) {
            size_t row = ((size_t)o * 64 + l) * KDIM + i0;
            for (int kk = lane; kk < 128; kk += 32) {
                g_Wf[row + kk] = __float2half(t[kk][l]);
            }
        }
    }
}

// ---------------- kernel 4: fp16 HMMA GEMM + fused leaf contraction ----------------
__device__ __forceinline__ void issue_chunk(int c, uint32_t sbu, int tid, size_t m0, size_t n0)
{
    if (c >= NCH) { cp_commit(); return; }   // empty group keeps wait_group accounting safe
    int s = c % NSTAGE;
    int koff = c * BK;
    uint32_t aBase = sbu + s * STAGE_B;
    uint32_t bBase = aBase + A_STAGE_B;
    // A tile: 128 rows x 64B = 512 x 16B
    #pragma unroll
    for (int i = 0; i < 2; i++) {
        int idx = tid + i * 256;
        int row = idx >> 2, seg = idx & 3;
        cp_async16(aBase + row * (STRIDE * 2) + seg * 16,
                   g_Af + (m0 + row) * KDIM + koff + seg * 8);
    }
    // B tile: 256 rows x 64B = 1024 x 16B
    #pragma unroll
    for (int i = 0; i < 4; i++) {
        int idx = tid + i * 256;
        int row = idx >> 2, seg = idx & 3;
        cp_async16(bBase + row * (STRIDE * 2) + seg * 16,
                   g_Wf + (n0 + row) * KDIM + koff + seg * 8);
    }
    cp_commit();
}

__global__ void __launch_bounds__(256, 1) gemm_kernel(
    const float* __restrict__ pb, float* __restrict__ out)
{
    extern __shared__ char smem[];
    uint32_t sbu = smem_u32(smem);
    int tid = threadIdx.x;
    int wid = tid >> 5;
    int lane = tid & 31;
    int wm = wid & 1;          // 2 m-warps (64 each)
    int wn = wid >> 1;         // 4 n-warps (64 each) -> one o per warp
    size_t m0 = (size_t)blockIdx.x * BM;   // m fastest: 8 m-blocks share W tiles in-wave
    size_t n0 = (size_t)blockIdx.y * BN;

    float acc[4][8][4];
    #pragma unroll
    for (int a = 0; a < 4; a++)
        #pragma unroll
        for (int b = 0; b < 8; b++)
            #pragma unroll
            for (int cc = 0; cc < 4; cc++) acc[a][b][cc] = 0.f;

    // ldmatrix per-lane address components
    int a_row = lane & 15;
    int a_k   = (lane >> 4) << 3;
    int b_row = (lane & 7) + ((lane >> 4) << 3);
    int b_k   = lane & 8;

    issue_chunk(0, sbu, tid, m0, n0);
    issue_chunk(1, sbu, tid, m0, n0);
    issue_chunk(2, sbu, tid, m0, n0);
    issue_chunk(3, sbu, tid, m0, n0);

    // 8 iterations, 2 chunks per barrier
    for (int p = 0; p < NCH / 2; p++) {
        cp_wait2();            // chunks 2p, 2p+1 complete (newest 2 groups may be in flight)
        __syncthreads();
        issue_chunk(2 * p + 4, sbu, tid, m0, n0);
        issue_chunk(2 * p + 5, sbu, tid, m0, n0);

        #pragma unroll
        for (int cc = 0; cc < 2; cc++) {
            int c = 2 * p + cc;
            int s = c % NSTAGE;
            uint32_t aBase = sbu + s * STAGE_B;
            uint32_t bBase = aBase + A_STAGE_B;
            #pragma unroll
            for (int kk = 0; kk < 2; kk++) {
                uint32_t af[4][4], bf[4][4];
                #pragma unroll
                for (int mi = 0; mi < 4; mi++) {
                    uint32_t addr = aBase + (uint32_t)((wm * 64 + mi * 16 + a_row) * (STRIDE * 2)
                                   + (kk * 16 + a_k) * 2);
                    ldsm_x4(af[mi], addr);
                }
                #pragma unroll
                for (int ni = 0; ni < 4; ni++) {
                    uint32_t addr = bBase + (uint32_t)((wn * 64 + ni * 16 + b_row) * (STRIDE * 2)
                                   + (kk * 16 + b_k) * 2);
                    ldsm_x4(bf[ni], addr);
                }
                #pragma unroll
                for (int mi = 0; mi < 4; mi++) {
                    #pragma unroll
                    for (int ni = 0; ni < 4; ni++) {
                        mma_f16(acc[mi][ni * 2 + 0], af[mi], bf[ni][0], bf[ni][1]);
                        mma_f16(acc[mi][ni * 2 + 1], af[mi], bf[ni][2], bf[ni][3]);
                    }
                }
            }
        }
    }

    // ---- fused epilogue: out[b,o] = sum_l P[b,l] * (R[b,o*64+l] + pb[o,l]) ----
    // Each warp column (wn) covers exactly one o with all 64 leaves.
    int o = (int)(n0 >> 6) + wn;
    const float* pbrow = pb + (size_t)o * NLEAF;
    #pragma unroll
    for (int mi = 0; mi < 4; mi++) {
        size_t r0 = m0 + wm * 64 + mi * 16 + (lane >> 2);
        const float* P0 = g_P + r0 * NLEAF;
        const float* P1 = g_P + (r0 + 8) * NLEAF;
        float s0 = 0.f, s1 = 0.f;
        #pragma unroll
        for (int ni = 0; ni < 4; ni++) {
            #pragma unroll
            for (int sub = 0; sub < 2; sub++) {
                int nf = ni * 2 + sub;
                int col = ni * 16 + sub * 8 + (lane & 3) * 2;
                float2 bv  = *(const float2*)(pbrow + col);
                float2 pv0 = *(const float2*)(P0 + col);
                float2 pv1 = *(const float2*)(P1 + col);
                s0 += (acc[mi][nf][0] + bv.x) * pv0.x + (acc[mi][nf][1] + bv.y) * pv0.y;
                s1 += (acc[mi][nf][2] + bv.x) * pv1.x + (acc[mi][nf][3] + bv.y) * pv1.y;
            }
        }
        s0 += __shfl_xor_sync(0xFFFFFFFFu, s0, 1);
        s0 += __shfl_xor_sync(0xFFFFFFFFu, s0, 2);
        s1 += __shfl_xor_sync(0xFFFFFFFFu, s1, 1);
        s1 += __shfl_xor_sync(0xFFFFFFFFu, s1, 2);
        if ((lane & 3) == 0) {
            out[r0 * OUTF + o] = s0;
            out[(r0 + 8) * OUTF + o] = s1;
        }
    }
}

// ---------------- launch ----------------
extern "C" void kernel_launch(void* const* d_in, const int* in_sizes, int n_in,
                              void* d_out, int out_size)
{
    const float* xg = (const float*)d_in[0];
    const float* xl = (const float*)d_in[1];
    const float* gw = (const float*)d_in[2];
    const float* gb = (const float*)d_in[3];
    const float* pw = (const float*)d_in[4];
    const float* pb = (const float*)d_in[5];
    float* out = (float*)d_out;

    cudaFuncSetAttribute(gemm_kernel, cudaFuncAttributeMaxDynamicSharedMemorySize, SM_TOTAL);

    gating_kernel<<<B_SZ / 4, 256>>>(xg, gw, gb);
    xconv_kernel<<<(B_SZ * KDIM) / 256, 256>>>(xl);
    repack_kernel<<<OUTF, 256>>>(pw);
    gemm_kernel<<<dim3(B_SZ / BM, NTOT / BN), 256, SM_TOTAL>>>(pb, out);
}